// round 16
// baseline (speedup 1.0000x reference)
#include <cuda_runtime.h>
#include <cuda_fp16.h>
#include <cstdint>

#define HD 512
#define BB 32
#define SN 400
#define TT 400
#define NBLK 128
#define TPB 512
#define NTHREADS (NBLK*TPB)
#define NWARP (NTHREADS/32)   // 2048

// ---------------- persistent device scratch (no allocations) ----------------
__device__ __half g_PencH[(size_t)SN*BB*HD];  // 13 MB: fc_W @ enc (fp16)
__device__ __half g_encH[(size_t)SN*BB*HD];   // 13 MB: enc in fp16
__device__ __half g_PhH[BB*HD];               // fc_W @ h (fp16)
__device__ __half g_awH[HD];                  // att_w fp16
__device__ float  g_gh[BB*3*HD];              // Whh @ h
__device__ float  g_gix[2][BB*3*HD];          // x @ Wih_x^T (double buffered)
__device__ float  g_e[BB*SN];                 // attention logits [b][s]
__device__ float  g_ctx[BB*HD];               // context
__device__ float  g_hst[2][BB*HD];            // hidden double buffer
__device__ unsigned g_flag[NBLK];             // barrier flags (monotonic)

__device__ __forceinline__ float tanha(float x) {
    float y;
    asm("tanh.approx.f32 %0, %1;" : "=f"(y) : "f"(x));
    return y;
}

__device__ __forceinline__ float warpsum(float v) {
#pragma unroll
    for (int o = 16; o > 0; o >>= 1) v += __shfl_xor_sync(0xffffffffu, v, o);
    return v;
}

__device__ __forceinline__ float dot4(float4 a, float4 b, float acc) {
    return fmaf(a.x, b.x, fmaf(a.y, b.y, fmaf(a.z, b.z, fmaf(a.w, b.w, acc))));
}

__device__ __forceinline__ unsigned ldv(const unsigned* p) {
    unsigned v;
    asm volatile("ld.volatile.global.u32 %0, [%1];" : "=r"(v) : "l"(p) : "memory");
    return v;
}
__device__ __forceinline__ void stv(unsigned* p, unsigned v) {
    asm volatile("st.volatile.global.u32 [%0], %1;" :: "l"(p), "r"(v) : "memory");
}

// grid barrier via per-block monotonic flags (replay-safe; no atomic serialization)
__device__ __forceinline__ void gridbar(int bid, int tid, unsigned target) {
    __syncthreads();
    __threadfence();                 // release + L1 flush (CCTL.IVALL on sm_103a)
    if (tid == 0) stv(&g_flag[bid], target);
    if (tid < 32) {
        for (;;) {
            unsigned a = ldv(&g_flag[tid]);
            unsigned b = ldv(&g_flag[tid + 32]);
            unsigned c = ldv(&g_flag[tid + 64]);
            unsigned d = ldv(&g_flag[tid + 96]);
            unsigned m = min(min(a, b), min(c, d));
            if (__all_sync(0xffffffffu, m >= target)) break;
        }
        __threadfence();             // acquire + L1 flush
    }
    __syncthreads();
}

// one half2-word term of the attention logit dot
__device__ __forceinline__ float term2(unsigned a, unsigned h, unsigned w, float acc) {
    float2 af = __half22float2(*(const __half2*)&a);
    float2 hf = __half22float2(*(const __half2*)&h);
    float2 wf = __half22float2(*(const __half2*)&w);
    acc = fmaf(tanha(af.x + hf.x), wf.x, acc);
    acc = fmaf(tanha(af.y + hf.y), wf.y, acc);
    return acc;
}

__global__ void __launch_bounds__(TPB)
decoder_kernel(const float* __restrict__ dec,   // (T,B,H)
               const float* __restrict__ enc,   // (S,B,H)
               const float* __restrict__ fcW,   // (H,H)
               const float* __restrict__ attw,  // (H)
               const float* __restrict__ Wih,   // (3H,2H)
               const float* __restrict__ Whh,   // (3H,H)
               const float* __restrict__ specW, // (H,H)
               const float* __restrict__ specb, // (H)
               const float* __restrict__ gateW, // (H)
               const float* __restrict__ gateb, // (1)
               float* __restrict__ out)         // B*T*H mel + B*T gate
{
    const int tid  = threadIdx.x;
    const int bid  = blockIdx.x;
    const int gtid = bid * TPB + tid;
    const int wl   = tid >> 5;
    const int wid  = gtid >> 5;
    const int lane = tid & 31;

    __shared__ float As[16][132];
    __shared__ float Bs[16][68];
    __shared__ float s_alpha[SN];
    __shared__ float s_red[TPB];
    __shared__ float s_part[32][132];
    __shared__ float s_ws[16][64];

    const unsigned bar0 = g_flag[bid];   // own flag: monotonic across replays
    unsigned nb = 0;

    // -------- init recurrent state (h0=0, x0=0) + fp16 conversions --------
    {
        __half2 z2 = __floats2half2_rn(0.f, 0.f);
        for (int i = gtid; i < BB*HD/2; i += NTHREADS) ((__half2*)g_PhH)[i] = z2;
        for (int i = gtid; i < BB*HD; i += NTHREADS) g_hst[0][i] = 0.f;
        for (int i = gtid; i < BB*3*HD; i += NTHREADS) { g_gh[i] = 0.f; g_gix[0][i] = 0.f; }
        for (int i = gtid; i < (SN*BB*HD)/2; i += NTHREADS) {
            float2 v = ((const float2*)enc)[i];
            ((__half2*)g_encH)[i] = __floats2half2_rn(v.x, v.y);
        }
        if (gtid < HD/2) {
            float2 v = ((const float2*)attw)[gtid];
            ((__half2*)g_awH)[gtid] = __floats2half2_rn(v.x, v.y);
        }
    }

    // -------- Penc GEMM: Penc[m][e] = sum_k enc[m*H+k]*fcW[e*H+k] (fp32 -> half) --------
    {
        const int tm = (tid >> 4) << 2;
        const int tn = (tid & 15) << 2;
        const int NT = (SN*BB/128) * (HD/64);   // 800 tiles
        for (int tile = bid; tile < NT; tile += NBLK) {
            const int m0 = (tile >> 3) * 128;
            const int n0 = (tile & 7) * 64;
            float acc[4][4];
#pragma unroll
            for (int i = 0; i < 4; ++i)
#pragma unroll
                for (int j = 0; j < 4; ++j) acc[i][j] = 0.f;

            for (int k0 = 0; k0 < HD; k0 += 16) {
                {
                    int m = tid >> 2, kq = (tid & 3) << 2;
                    float4 v = *(const float4*)(enc + (size_t)(m0 + m) * HD + k0 + kq);
                    As[kq+0][m] = v.x; As[kq+1][m] = v.y; As[kq+2][m] = v.z; As[kq+3][m] = v.w;
                }
                if (tid < 256) {
                    int n = tid >> 2, kq = (tid & 3) << 2;
                    float4 v = *(const float4*)(fcW + (size_t)(n0 + n) * HD + k0 + kq);
                    Bs[kq+0][n] = v.x; Bs[kq+1][n] = v.y; Bs[kq+2][n] = v.z; Bs[kq+3][n] = v.w;
                }
                __syncthreads();
#pragma unroll
                for (int kk = 0; kk < 16; ++kk) {
                    float4 a = *(const float4*)&As[kk][tm];
                    float4 b = *(const float4*)&Bs[kk][tn];
                    float av[4] = {a.x, a.y, a.z, a.w};
                    float bv[4] = {b.x, b.y, b.z, b.w};
#pragma unroll
                    for (int i = 0; i < 4; ++i)
#pragma unroll
                        for (int j = 0; j < 4; ++j)
                            acc[i][j] = fmaf(av[i], bv[j], acc[i][j]);
                }
                __syncthreads();
            }
#pragma unroll
            for (int i = 0; i < 4; ++i) {
                __half* row = g_PencH + (size_t)(m0 + tm + i) * HD + n0 + tn;
                *(__half2*)(row)     = __floats2half2_rn(acc[i][0], acc[i][1]);
                *(__half2*)(row + 2) = __floats2half2_rn(acc[i][2], acc[i][3]);
            }
        }
    }
    gridbar(bid, tid, bar0 + (++nb));

    int cur = 0;
    for (int t = 0; t < TT; ++t) {
        const int nxt = cur ^ 1;

        // ======== P2: e[b][s] = sum_e attw[e]*tanh(Ph[b,e]+Penc[s,b,e]) ========
        {
            const int s0 = (int)(((long long)wid * (SN*BB)) / NWARP);
            const int s1 = (int)(((long long)(wid+1) * (SN*BB)) / NWARP);
            for (int p = s0; p < s1; ++p) {
                const int b = p & 31;
                const __half* pe = g_PencH + (size_t)p * HD;
                const __half* ph = g_PhH + b * HD;
                float acc = 0.f;
#pragma unroll
                for (int sg = 0; sg < 2; ++sg) {
                    int off = sg * 256 + lane * 8;
                    uint4 pv = *(const uint4*)(pe + off);
                    uint4 hv = *(const uint4*)(ph + off);
                    uint4 wv = *(const uint4*)(g_awH + off);
                    acc = term2(pv.x, hv.x, wv.x, acc);
                    acc = term2(pv.y, hv.y, wv.y, acc);
                    acc = term2(pv.z, hv.z, wv.z, acc);
                    acc = term2(pv.w, hv.w, wv.w, acc);
                }
                acc = warpsum(acc);
                if (lane == 0) g_e[b * SN + (p >> 5)] = acc;
            }
        }
        gridbar(bid, tid, bar0 + (++nb));

        // ======== P3: softmax over s (per b) + ctx[b,:] ========
        {
            const int b = bid & 31;
            const int h0 = (bid >> 5) << 7;
            float v = (tid < SN) ? g_e[b * SN + tid] : -3.0e38f;
            s_red[tid] = v;
            __syncthreads();
            for (int o = TPB >> 1; o > 0; o >>= 1) {
                if (tid < o) s_red[tid] = fmaxf(s_red[tid], s_red[tid + o]);
                __syncthreads();
            }
            float mx = s_red[0];
            __syncthreads();
            float ex = (tid < SN) ? __expf(v - mx) : 0.f;
            if (tid < SN) s_alpha[tid] = ex;
            s_red[tid] = ex;
            __syncthreads();
            for (int o = TPB >> 1; o > 0; o >>= 1) {
                if (tid < o) s_red[tid] += s_red[tid + o];
                __syncthreads();
            }
            float inv = 1.f / s_red[0];
            __syncthreads();

            const int hg = tid & 15;          // 16 groups of 8 h
            const int sp = tid >> 4;          // 32-way s split
            float acc[8];
#pragma unroll
            for (int i = 0; i < 8; ++i) acc[i] = 0.f;
            for (int s = sp; s < SN; s += 32) {
                float a = s_alpha[s];
                uint4 ev = *(const uint4*)(g_encH + ((size_t)(s * BB + b)) * HD + h0 + hg * 8);
                float2 e0 = __half22float2(*(const __half2*)&ev.x);
                float2 e1 = __half22float2(*(const __half2*)&ev.y);
                float2 e2 = __half22float2(*(const __half2*)&ev.z);
                float2 e3 = __half22float2(*(const __half2*)&ev.w);
                acc[0] = fmaf(a, e0.x, acc[0]); acc[1] = fmaf(a, e0.y, acc[1]);
                acc[2] = fmaf(a, e1.x, acc[2]); acc[3] = fmaf(a, e1.y, acc[3]);
                acc[4] = fmaf(a, e2.x, acc[4]); acc[5] = fmaf(a, e2.y, acc[5]);
                acc[6] = fmaf(a, e3.x, acc[6]); acc[7] = fmaf(a, e3.y, acc[7]);
            }
            *(float4*)&s_part[sp][hg * 8]     = make_float4(acc[0], acc[1], acc[2], acc[3]);
            *(float4*)&s_part[sp][hg * 8 + 4] = make_float4(acc[4], acc[5], acc[6], acc[7]);
            __syncthreads();
            if (tid < 128) {
                float s = 0.f;
#pragma unroll
                for (int k = 0; k < 32; ++k) s += s_part[k][tid];
                g_ctx[b * HD + h0 + tid] = s * inv;
            }
        }
        gridbar(bid, tid, bar0 + (++nb));

        // ======== P4: GRU update + gix for next step ========
        {
            const int NT4 = 1024 + 1536;
            const int s0 = (int)(((long long)wid * NT4) / NWARP);
            const int s1 = (int)(((long long)(wid+1) * NT4) / NWARP);
            for (int task = s0; task < s1; ++task) {
                if (task < 1024) {
                    // GRU column j for 16 b
                    const int j  = task >> 1;
                    const int bh = (task & 1) << 4;
                    float4 wr[4], wz[4], wn[4];
#pragma unroll
                    for (int i = 0; i < 4; ++i) {
                        int idx = lane + (i << 5);
                        wr[i] = ((const float4*)(Wih + (size_t)j * 1024 + 512))[idx];
                        wz[i] = ((const float4*)(Wih + (size_t)(512 + j) * 1024 + 512))[idx];
                        wn[i] = ((const float4*)(Wih + (size_t)(1024 + j) * 1024 + 512))[idx];
                    }
                    float* ws = s_ws[wl];
#pragma unroll
                    for (int hf = 0; hf < 2; ++hf) {
                        float ar[8], az[8], an[8];
#pragma unroll
                        for (int bi = 0; bi < 8; ++bi) { ar[bi] = az[bi] = an[bi] = 0.f; }
#pragma unroll
                        for (int bi = 0; bi < 8; ++bi) {
                            const float4* c4 = (const float4*)(g_ctx + (bh + hf * 8 + bi) * HD);
#pragma unroll
                            for (int i = 0; i < 4; ++i) {
                                float4 c = c4[lane + (i << 5)];
                                ar[bi] = dot4(c, wr[i], ar[bi]);
                                az[bi] = dot4(c, wz[i], az[bi]);
                                an[bi] = dot4(c, wn[i], an[bi]);
                            }
                        }
#pragma unroll
                        for (int bi = 0; bi < 8; ++bi) {
                            ar[bi] = warpsum(ar[bi]);
                            az[bi] = warpsum(az[bi]);
                            an[bi] = warpsum(an[bi]);
                        }
                        if (lane == 0) {
#pragma unroll
                            for (int bi = 0; bi < 8; ++bi) {
                                int q = hf * 8 + bi;
                                ws[q] = ar[bi]; ws[16 + q] = az[bi]; ws[32 + q] = an[bi];
                            }
                        }
                    }
                    __syncwarp();
                    if (lane < 16) {
                        const int b = bh + lane;
                        float ar = ws[lane], az = ws[16 + lane], an = ws[32 + lane];
                        const float* gx = g_gix[cur] + b * 1536;
                        const float* gg = g_gh + b * 1536;
                        float ir  = gx[j] + ar + gg[j];
                        float iz  = gx[512 + j] + az + gg[512 + j];
                        float inn = gx[1024 + j] + an;
                        float hn  = gg[1024 + j];
                        float r = 1.f / (1.f + __expf(-ir));
                        float z = 1.f / (1.f + __expf(-iz));
                        float n = tanhf(fmaf(r, hn, inn));
                        float hp = g_hst[cur][b * HD + j];
                        g_hst[nxt][b * HD + j] = fmaf(z, hp - n, n);
                    }
                    __syncwarp();
                } else {
                    // gix rows 4*rg..+3 vs x_{t+1} = dec[t], 8 b per task
                    const int t2 = task - 1024;
                    const int rg = t2 >> 2, bq = t2 & 3;
                    const int r0 = rg << 2, b0 = bq << 3;
                    float4 w[4][4];
#pragma unroll
                    for (int r = 0; r < 4; ++r) {
                        const float4* Wp = (const float4*)(Wih + (size_t)(r0 + r) * 1024);
#pragma unroll
                        for (int i = 0; i < 4; ++i) w[r][i] = Wp[lane + (i << 5)];
                    }
                    const float* x = dec + (size_t)t * BB * HD;
                    float* gxo = g_gix[nxt];
#pragma unroll
                    for (int hf = 0; hf < 2; ++hf) {
                        float acc[4][4];
#pragma unroll
                        for (int r = 0; r < 4; ++r)
#pragma unroll
                            for (int bi = 0; bi < 4; ++bi) acc[r][bi] = 0.f;
#pragma unroll
                        for (int bi = 0; bi < 4; ++bi) {
                            const int b = b0 + hf * 4 + bi;
                            const float4* xb = (const float4*)(x + b * HD);
                            float4 h4[4];
#pragma unroll
                            for (int i = 0; i < 4; ++i) h4[i] = xb[lane + (i << 5)];
#pragma unroll
                            for (int r = 0; r < 4; ++r)
#pragma unroll
                                for (int i = 0; i < 4; ++i)
                                    acc[r][bi] = dot4(h4[i], w[r][i], acc[r][bi]);
                        }
#pragma unroll
                        for (int r = 0; r < 4; ++r)
#pragma unroll
                            for (int bi = 0; bi < 4; ++bi) acc[r][bi] = warpsum(acc[r][bi]);
                        if (lane == 0) {
#pragma unroll
                            for (int r = 0; r < 4; ++r)
#pragma unroll
                                for (int bi = 0; bi < 4; ++bi)
                                    gxo[(b0 + hf * 4 + bi) * 1536 + r0 + r] = acc[r][bi];
                        }
                    }
                }
            }
        }
        gridbar(bid, tid, bar0 + (++nb));

        // ======== Epilogue: mel/gate outputs + next-step Ph, gh ========
        {
            const float* h2 = g_hst[nxt];
            const int NTE = 2562;
            const int s0 = (int)(((long long)wid * NTE) / NWARP);
            const int s1 = (int)(((long long)(wid+1) * NTE) / NWARP);
            for (int task = s0; task < s1; ++task) {
                if (task < 2560) {
                    const int rg = task >> 2, bq = task & 3;
                    const int r0 = rg << 2, b0 = bq << 3;
                    const float* W;
                    int mode, rb;
                    if (r0 < 512)       { rb = r0;        W = specW + (size_t)rb * HD; mode = 0; }
                    else if (r0 < 1024) { rb = r0 - 512;  W = fcW   + (size_t)rb * HD; mode = 1; }
                    else                { rb = r0 - 1024; W = Whh   + (size_t)rb * HD; mode = 2; }
                    float4 w[4][4];
#pragma unroll
                    for (int r = 0; r < 4; ++r) {
                        const float4* Wp = (const float4*)(W + (size_t)r * HD);
#pragma unroll
                        for (int i = 0; i < 4; ++i) w[r][i] = Wp[lane + (i << 5)];
                    }
#pragma unroll
                    for (int hf = 0; hf < 2; ++hf) {
                        float acc[4][4];
#pragma unroll
                        for (int r = 0; r < 4; ++r)
#pragma unroll
                            for (int bi = 0; bi < 4; ++bi) acc[r][bi] = 0.f;
#pragma unroll
                        for (int bi = 0; bi < 4; ++bi) {
                            const int b = b0 + hf * 4 + bi;
                            const float4* hb = (const float4*)(h2 + b * HD);
                            float4 h4[4];
#pragma unroll
                            for (int i = 0; i < 4; ++i) h4[i] = hb[lane + (i << 5)];
#pragma unroll
                            for (int r = 0; r < 4; ++r)
#pragma unroll
                                for (int i = 0; i < 4; ++i)
                                    acc[r][bi] = dot4(h4[i], w[r][i], acc[r][bi]);
                        }
#pragma unroll
                        for (int r = 0; r < 4; ++r)
#pragma unroll
                            for (int bi = 0; bi < 4; ++bi) acc[r][bi] = warpsum(acc[r][bi]);
                        if (lane == 0) {
#pragma unroll
                            for (int bi = 0; bi < 4; ++bi) {
                                const int b = b0 + hf * 4 + bi;
                                if (mode == 0) {
#pragma unroll
                                    for (int r = 0; r < 4; ++r)
                                        out[(size_t)b * TT * HD + (size_t)t * HD + rb + r] =
                                            acc[r][bi] + specb[rb + r];
                                } else if (mode == 1) {
#pragma unroll
                                    for (int r = 0; r < 4; ++r)
                                        g_PhH[b * HD + rb + r] = __float2half(acc[r][bi]);
                                } else {
#pragma unroll
                                    for (int r = 0; r < 4; ++r)
                                        g_gh[b * 1536 + rb + r] = acc[r][bi];
                                }
                            }
                        }
                    }
                } else {
                    // gate outputs, 16 b per task
                    const int b0 = (task - 2560) << 4;
                    float4 w[4];
#pragma unroll
                    for (int i = 0; i < 4; ++i) w[i] = ((const float4*)gateW)[lane + (i << 5)];
#pragma unroll
                    for (int hf = 0; hf < 2; ++hf) {
                        float acc[8];
#pragma unroll
                        for (int bi = 0; bi < 8; ++bi) acc[bi] = 0.f;
#pragma unroll
                        for (int bi = 0; bi < 8; ++bi) {
                            const float4* hb = (const float4*)(h2 + (b0 + hf * 8 + bi) * HD);
#pragma unroll
                            for (int i = 0; i < 4; ++i)
                                acc[bi] = dot4(hb[lane + (i << 5)], w[i], acc[bi]);
                        }
#pragma unroll
                        for (int bi = 0; bi < 8; ++bi) acc[bi] = warpsum(acc[bi]);
                        if (lane == 0) {
                            float gb = gateb[0];
#pragma unroll
                            for (int bi = 0; bi < 8; ++bi)
                                out[(size_t)BB * TT * HD + (size_t)(b0 + hf * 8 + bi) * TT + t] =
                                    acc[bi] + gb;
                        }
                    }
                }
            }
        }
        gridbar(bid, tid, bar0 + (++nb));

        cur ^= 1;
    }
}

extern "C" void kernel_launch(void* const* d_in, const int* in_sizes, int n_in,
                              void* d_out, int out_size) {
    (void)in_sizes; (void)n_in; (void)out_size;
    decoder_kernel<<<NBLK, TPB>>>(
        (const float*)d_in[0],   // decoder_inputs
        (const float*)d_in[1],   // alignment_inputs
        (const float*)d_in[2],   // fc_W
        (const float*)d_in[3],   // att_w
        (const float*)d_in[4],   // Wih
        (const float*)d_in[5],   // Whh
        (const float*)d_in[6],   // spec_W
        (const float*)d_in[7],   // spec_b
        (const float*)d_in[8],   // gate_W
        (const float*)d_in[9],   // gate_b
        (float*)d_out);
}

// round 17
// speedup vs baseline: 1.9072x; 1.9072x over previous
#include <cuda_runtime.h>
#include <cuda_fp16.h>
#include <cstdint>

#define HD 512
#define BB 32
#define SN 400
#define TT 400
#define NBLK 128
#define TPB 512
#define NTHREADS (NBLK*TPB)
#define NWARP (NTHREADS/32)   // 2048

typedef unsigned long long u64;

// ---------------- persistent device scratch (no allocations) ----------------
__device__ __align__(16) __half g_PencH[(size_t)SN*BB*HD];  // fc_W @ enc (fp16)
__device__ __align__(16) __half g_encH[(size_t)SN*BB*HD];   // enc fp16
__device__ __align__(16) __half g_PhH[BB*HD];               // fc_W @ h (fp16)
__device__ __align__(16) __half g_awH[HD];                  // att_w fp16
__device__ __align__(16) float  g_gh[BB*3*HD];              // Whh @ h
__device__ __align__(16) float  g_gix[2][BB*3*HD];          // x @ Wih_x^T (dbl buf)
__device__ __align__(16) float  g_e[BB*SN];                 // logits [b][s]
__device__ __align__(16) float  g_ctx[BB*HD];               // context
__device__ __align__(16) float  g_hst[2][BB*HD];            // hidden dbl buf

// hierarchical monotonic barrier state (zero-init; never reset -> replay safe)
__device__ u64 g_cellc[8];
__device__ u64 g_master;
__device__ u64 g_rel2;

__device__ __forceinline__ float tanha(float x) {
    float y;
    asm("tanh.approx.f32 %0, %1;" : "=f"(y) : "f"(x));
    return y;
}

__device__ __forceinline__ float warpsum(float v) {
#pragma unroll
    for (int o = 16; o > 0; o >>= 1) v += __shfl_xor_sync(0xffffffffu, v, o);
    return v;
}

// packed fp32x2 FMA (Blackwell FFMA2): d = a*b + c elementwise on 2 packed floats
__device__ __forceinline__ u64 fma2(u64 a, u64 b, u64 c) {
    u64 d;
    asm("fma.rn.f32x2 %0, %1, %2, %3;" : "=l"(d) : "l"(a), "l"(b), "l"(c));
    return d;
}
__device__ __forceinline__ float fcol(u64 a) {   // collapse packed pair to scalar
    union { u64 u; float2 f; } v;
    v.u = a;
    return v.f.x + v.f.y;
}

// grid barrier: tid0-only, 8-cell hierarchical arrive, monotonic counters
__device__ __forceinline__ void gridbar(int bid, u64 target) {
    __syncthreads();
    if (threadIdx.x == 0) {
        __threadfence();                                  // release + L1 flush
        u64 c = atomicAdd(&g_cellc[bid & 7], 1ULL) + 1ULL;
        if ((c & 15ULL) == 0ULL) {                        // 16 blocks per cell
            u64 m = atomicAdd(&g_master, 1ULL) + 1ULL;
            if ((m & 7ULL) == 0ULL)
                atomicExch(&g_rel2, m >> 3);
        }
        while (*(volatile u64*)&g_rel2 < target) { }
        __threadfence();                                  // acquire + L1 flush
    }
    __syncthreads();
}

// one half2-word term of the attention logit dot
__device__ __forceinline__ float term2(unsigned a, unsigned h, unsigned w, float acc) {
    float2 af = __half22float2(*(const __half2*)&a);
    float2 hf = __half22float2(*(const __half2*)&h);
    float2 wf = __half22float2(*(const __half2*)&w);
    acc = fmaf(tanha(af.x + hf.x), wf.x, acc);
    acc = fmaf(tanha(af.y + hf.y), wf.y, acc);
    return acc;
}

__global__ void __launch_bounds__(TPB)
decoder_kernel(const float* __restrict__ dec,   // (T,B,H)
               const float* __restrict__ enc,   // (S,B,H)
               const float* __restrict__ fcW,   // (H,H)
               const float* __restrict__ attw,  // (H)
               const float* __restrict__ Wih,   // (3H,2H)
               const float* __restrict__ Whh,   // (3H,H)
               const float* __restrict__ specW, // (H,H)
               const float* __restrict__ specb, // (H)
               const float* __restrict__ gateW, // (H)
               const float* __restrict__ gateb, // (1)
               float* __restrict__ out)         // B*T*H mel + B*T gate
{
    const int tid  = threadIdx.x;
    const int bid  = blockIdx.x;
    const int gtid = bid * TPB + tid;
    const int wl   = tid >> 5;
    const int wid  = gtid >> 5;
    const int lane = tid & 31;

    __shared__ float As[16][132];
    __shared__ float Bs[16][68];
    __shared__ float s_alpha[SN];
    __shared__ float s_red[TPB];
    __shared__ float s_part[32][132];
    __shared__ float s_ws[16][64];

    const u64 bar0 = *(volatile u64*)&g_rel2;   // monotonic base across replays
    u64 nb = 0;

    // -------- init recurrent state (h0=0, x0=0) + fp16 conversions --------
    {
        __half2 z2 = __floats2half2_rn(0.f, 0.f);
        for (int i = gtid; i < BB*HD/2; i += NTHREADS) ((__half2*)g_PhH)[i] = z2;
        for (int i = gtid; i < BB*HD; i += NTHREADS) g_hst[0][i] = 0.f;
        for (int i = gtid; i < BB*3*HD; i += NTHREADS) { g_gh[i] = 0.f; g_gix[0][i] = 0.f; }
        for (int i = gtid; i < (SN*BB*HD)/2; i += NTHREADS) {
            float2 v = ((const float2*)enc)[i];
            ((__half2*)g_encH)[i] = __floats2half2_rn(v.x, v.y);
        }
        if (gtid < HD/2) {
            float2 v = ((const float2*)attw)[gtid];
            ((__half2*)g_awH)[gtid] = __floats2half2_rn(v.x, v.y);
        }
    }

    // -------- Penc GEMM: Penc[m][e] = sum_k enc[m*H+k]*fcW[e*H+k] (fp32 -> half) ----
    {
        const int tm = (tid >> 4) << 2;
        const int tn = (tid & 15) << 2;
        const int NT = (SN*BB/128) * (HD/64);   // 800 tiles
        for (int tile = bid; tile < NT; tile += NBLK) {
            const int m0 = (tile >> 3) * 128;
            const int n0 = (tile & 7) * 64;
            float acc[4][4];
#pragma unroll
            for (int i = 0; i < 4; ++i)
#pragma unroll
                for (int j = 0; j < 4; ++j) acc[i][j] = 0.f;

            for (int k0 = 0; k0 < HD; k0 += 16) {
                {
                    int m = tid >> 2, kq = (tid & 3) << 2;
                    float4 v = *(const float4*)(enc + (size_t)(m0 + m) * HD + k0 + kq);
                    As[kq+0][m] = v.x; As[kq+1][m] = v.y; As[kq+2][m] = v.z; As[kq+3][m] = v.w;
                }
                if (tid < 256) {
                    int n = tid >> 2, kq = (tid & 3) << 2;
                    float4 v = *(const float4*)(fcW + (size_t)(n0 + n) * HD + k0 + kq);
                    Bs[kq+0][n] = v.x; Bs[kq+1][n] = v.y; Bs[kq+2][n] = v.z; Bs[kq+3][n] = v.w;
                }
                __syncthreads();
#pragma unroll
                for (int kk = 0; kk < 16; ++kk) {
                    float4 a = *(const float4*)&As[kk][tm];
                    float4 b = *(const float4*)&Bs[kk][tn];
                    float av[4] = {a.x, a.y, a.z, a.w};
                    float bv[4] = {b.x, b.y, b.z, b.w};
#pragma unroll
                    for (int i = 0; i < 4; ++i)
#pragma unroll
                        for (int j = 0; j < 4; ++j)
                            acc[i][j] = fmaf(av[i], bv[j], acc[i][j]);
                }
                __syncthreads();
            }
#pragma unroll
            for (int i = 0; i < 4; ++i) {
                __half* row = g_PencH + (size_t)(m0 + tm + i) * HD + n0 + tn;
                *(__half2*)(row)     = __floats2half2_rn(acc[i][0], acc[i][1]);
                *(__half2*)(row + 2) = __floats2half2_rn(acc[i][2], acc[i][3]);
            }
        }
    }
    gridbar(bid, bar0 + (++nb));

    int cur = 0;
    for (int t = 0; t < TT; ++t) {
        const int nxt = cur ^ 1;

        // ======== P2: e[b][s] = sum_e attw[e]*tanh(Ph[b,e]+Penc[s,b,e]) ========
        {
            const int s0 = (int)(((long long)wid * (SN*BB)) >> 11);
            const int s1 = (int)(((long long)(wid+1) * (SN*BB)) >> 11);
            for (int p = s0; p < s1; ++p) {
                const int b = p & 31;
                const __half* pe = g_PencH + (size_t)p * HD;
                const __half* ph = g_PhH + b * HD;
                float acc = 0.f;
#pragma unroll
                for (int sg = 0; sg < 2; ++sg) {
                    int off = sg * 256 + lane * 8;
                    uint4 pv = *(const uint4*)(pe + off);
                    uint4 hv = *(const uint4*)(ph + off);
                    uint4 wv = *(const uint4*)(g_awH + off);
                    acc = term2(pv.x, hv.x, wv.x, acc);
                    acc = term2(pv.y, hv.y, wv.y, acc);
                    acc = term2(pv.z, hv.z, wv.z, acc);
                    acc = term2(pv.w, hv.w, wv.w, acc);
                }
                acc = warpsum(acc);
                if (lane == 0) g_e[b * SN + (p >> 5)] = acc;
            }
        }
        gridbar(bid, bar0 + (++nb));

        // ======== P3: softmax over s (per b) + ctx[b,:] ========
        {
            const int b = bid & 31;
            const int h0 = (bid >> 5) << 7;
            float v = (tid < SN) ? g_e[b * SN + tid] : -3.0e38f;
            s_red[tid] = v;
            __syncthreads();
            for (int o = TPB >> 1; o > 0; o >>= 1) {
                if (tid < o) s_red[tid] = fmaxf(s_red[tid], s_red[tid + o]);
                __syncthreads();
            }
            float mx = s_red[0];
            __syncthreads();
            float ex = (tid < SN) ? __expf(v - mx) : 0.f;
            if (tid < SN) s_alpha[tid] = ex;
            s_red[tid] = ex;
            __syncthreads();
            for (int o = TPB >> 1; o > 0; o >>= 1) {
                if (tid < o) s_red[tid] += s_red[tid + o];
                __syncthreads();
            }
            float inv = 1.f / s_red[0];
            __syncthreads();

            const int hg = tid & 15;
            const int sp = tid >> 4;
            float acc[8];
#pragma unroll
            for (int i = 0; i < 8; ++i) acc[i] = 0.f;
            for (int s = sp; s < SN; s += 32) {
                float a = s_alpha[s];
                uint4 ev = *(const uint4*)(g_encH + ((size_t)(s * BB + b)) * HD + h0 + hg * 8);
                float2 e0 = __half22float2(*(const __half2*)&ev.x);
                float2 e1 = __half22float2(*(const __half2*)&ev.y);
                float2 e2 = __half22float2(*(const __half2*)&ev.z);
                float2 e3 = __half22float2(*(const __half2*)&ev.w);
                acc[0] = fmaf(a, e0.x, acc[0]); acc[1] = fmaf(a, e0.y, acc[1]);
                acc[2] = fmaf(a, e1.x, acc[2]); acc[3] = fmaf(a, e1.y, acc[3]);
                acc[4] = fmaf(a, e2.x, acc[4]); acc[5] = fmaf(a, e2.y, acc[5]);
                acc[6] = fmaf(a, e3.x, acc[6]); acc[7] = fmaf(a, e3.y, acc[7]);
            }
            *(float4*)&s_part[sp][hg * 8]     = make_float4(acc[0], acc[1], acc[2], acc[3]);
            *(float4*)&s_part[sp][hg * 8 + 4] = make_float4(acc[4], acc[5], acc[6], acc[7]);
            __syncthreads();
            if (tid < 128) {
                float s = 0.f;
#pragma unroll
                for (int k = 0; k < 32; ++k) s += s_part[k][tid];
                g_ctx[b * HD + h0 + tid] = s * inv;
            }
        }
        gridbar(bid, bar0 + (++nb));

        // ======== P4: GRU update — 2048 tasks (j, 8 b), 3 gate rows resident ========
        {
            const int j  = wid >> 2;            // 0..511
            const int b0 = (wid & 3) << 3;      // 0,8,16,24
            ulonglong2 w[3][4];
#pragma unroll
            for (int g = 0; g < 3; ++g) {
                const ulonglong2* W = (const ulonglong2*)(Wih + (size_t)(g * 512 + j) * 1024 + 512);
#pragma unroll
                for (int i = 0; i < 4; ++i) w[g][i] = W[lane + (i << 5)];
            }
            float st[3][8];
#pragma unroll
            for (int bi = 0; bi < 8; ++bi) {
                const ulonglong2* c2 = (const ulonglong2*)(g_ctx + (b0 + bi) * HD);
                ulonglong2 c[4];
#pragma unroll
                for (int i = 0; i < 4; ++i) c[i] = c2[lane + (i << 5)];
                u64 a0 = 0ULL, a1 = 0ULL, a2 = 0ULL;
#pragma unroll
                for (int i = 0; i < 4; ++i) {
                    a0 = fma2(c[i].x, w[0][i].x, a0); a0 = fma2(c[i].y, w[0][i].y, a0);
                    a1 = fma2(c[i].x, w[1][i].x, a1); a1 = fma2(c[i].y, w[1][i].y, a1);
                    a2 = fma2(c[i].x, w[2][i].x, a2); a2 = fma2(c[i].y, w[2][i].y, a2);
                }
                st[0][bi] = fcol(a0); st[1][bi] = fcol(a1); st[2][bi] = fcol(a2);
            }
#pragma unroll
            for (int g = 0; g < 3; ++g)
#pragma unroll
                for (int bi = 0; bi < 8; ++bi) st[g][bi] = warpsum(st[g][bi]);
            if (lane == 0) {
#pragma unroll
                for (int g = 0; g < 3; ++g)
#pragma unroll
                    for (int bi = 0; bi < 8; ++bi) s_ws[wl][g * 8 + bi] = st[g][bi];
            }
            __syncwarp();
            if (lane < 8) {
                const int b = b0 + lane;
                float ar = s_ws[wl][lane], az = s_ws[wl][8 + lane], an = s_ws[wl][16 + lane];
                const float* gx = g_gix[cur] + b * 1536;
                const float* gg = g_gh + b * 1536;
                float ir  = gx[j] + ar + gg[j];
                float iz  = gx[512 + j] + az + gg[512 + j];
                float inn = gx[1024 + j] + an;
                float hn  = gg[1024 + j];
                float r = 1.f / (1.f + __expf(-ir));
                float z = 1.f / (1.f + __expf(-iz));
                float n = tanhf(fmaf(r, hn, inn));
                float hp = g_hst[cur][b * HD + j];
                g_hst[nxt][b * HD + j] = fmaf(z, hp - n, n);
            }
            __syncwarp();
        }
        gridbar(bid, bar0 + (++nb));

        // ======== Epilogue: 4096 tasks (4 rows x 8 b) over spec|fc|Whh|gix + gate ====
        {
            const float* h2 = g_hst[nxt];
            const float* xv = dec + (size_t)t * BB * HD;   // x_{t+1}
#pragma unroll
            for (int q = 0; q < 2; ++q) {
                const int tk = wid + q * 2048;
                const int rg = tk >> 2;            // 0..1023
                const int b0 = (tk & 3) << 3;
                const int r0 = rg << 2;            // 0..4092
                const float* W;
                const float* vec = h2;
                int stride = HD, mode, rb;
                if (r0 < 512)       { rb = r0;        W = specW + (size_t)rb * HD; mode = 0; }
                else if (r0 < 1024) { rb = r0 - 512;  W = fcW   + (size_t)rb * HD; mode = 1; }
                else if (r0 < 2560) { rb = r0 - 1024; W = Whh   + (size_t)rb * HD; mode = 2; }
                else { rb = r0 - 2560; W = Wih + (size_t)rb * 1024; stride = 1024; mode = 3; vec = xv; }

                ulonglong2 w[4][4];
#pragma unroll
                for (int r = 0; r < 4; ++r) {
                    const ulonglong2* Wp = (const ulonglong2*)(W + (size_t)r * stride);
#pragma unroll
                    for (int i = 0; i < 4; ++i) w[r][i] = Wp[lane + (i << 5)];
                }
#pragma unroll
                for (int hf = 0; hf < 2; ++hf) {
                    float st[4][4];
#pragma unroll
                    for (int bi = 0; bi < 4; ++bi) {
                        const int b = b0 + hf * 4 + bi;
                        const ulonglong2* v2 = (const ulonglong2*)(vec + (size_t)b * HD);
                        ulonglong2 h[4];
#pragma unroll
                        for (int i = 0; i < 4; ++i) h[i] = v2[lane + (i << 5)];
                        u64 acc[4] = {0ULL, 0ULL, 0ULL, 0ULL};
#pragma unroll
                        for (int r = 0; r < 4; ++r)
#pragma unroll
                            for (int i = 0; i < 4; ++i) {
                                acc[r] = fma2(h[i].x, w[r][i].x, acc[r]);
                                acc[r] = fma2(h[i].y, w[r][i].y, acc[r]);
                            }
#pragma unroll
                        for (int r = 0; r < 4; ++r) st[r][bi] = fcol(acc[r]);
                    }
#pragma unroll
                    for (int r = 0; r < 4; ++r)
#pragma unroll
                        for (int bi = 0; bi < 4; ++bi) st[r][bi] = warpsum(st[r][bi]);
                    if (lane == 0) {
#pragma unroll
                        for (int bi = 0; bi < 4; ++bi) {
                            const int b = b0 + hf * 4 + bi;
                            if (mode == 0) {
#pragma unroll
                                for (int r = 0; r < 4; ++r)
                                    out[(size_t)b * TT * HD + (size_t)t * HD + rb + r] =
                                        st[r][bi] + specb[rb + r];
                            } else if (mode == 1) {
#pragma unroll
                                for (int r = 0; r < 4; ++r)
                                    g_PhH[b * HD + rb + r] = __float2half(st[r][bi]);
                            } else if (mode == 2) {
#pragma unroll
                                for (int r = 0; r < 4; ++r)
                                    g_gh[b * 1536 + rb + r] = st[r][bi];
                            } else {
#pragma unroll
                                for (int r = 0; r < 4; ++r)
                                    g_gix[nxt][b * 1536 + rb + r] = st[r][bi];
                            }
                        }
                    }
                }
            }
            // gate outputs: warps 0 and 1, 16 b each
            if (wid < 2) {
                const int b0 = wid << 4;
                ulonglong2 w[4];
#pragma unroll
                for (int i = 0; i < 4; ++i) w[i] = ((const ulonglong2*)gateW)[lane + (i << 5)];
#pragma unroll
                for (int hf = 0; hf < 2; ++hf) {
                    float st[8];
#pragma unroll
                    for (int bi = 0; bi < 8; ++bi) {
                        const ulonglong2* v2 =
                            (const ulonglong2*)(h2 + (size_t)(b0 + hf * 8 + bi) * HD);
                        u64 acc = 0ULL;
#pragma unroll
                        for (int i = 0; i < 4; ++i) {
                            ulonglong2 h = v2[lane + (i << 5)];
                            acc = fma2(h.x, w[i].x, acc);
                            acc = fma2(h.y, w[i].y, acc);
                        }
                        st[bi] = fcol(acc);
                    }
#pragma unroll
                    for (int bi = 0; bi < 8; ++bi) st[bi] = warpsum(st[bi]);
                    if (lane == 0) {
                        float gb = gateb[0];
#pragma unroll
                        for (int bi = 0; bi < 8; ++bi)
                            out[(size_t)BB * TT * HD + (size_t)(b0 + hf * 8 + bi) * TT + t] =
                                st[bi] + gb;
                    }
                }
            }
        }
        gridbar(bid, bar0 + (++nb));

        cur ^= 1;
    }
}

extern "C" void kernel_launch(void* const* d_in, const int* in_sizes, int n_in,
                              void* d_out, int out_size) {
    (void)in_sizes; (void)n_in; (void)out_size;
    decoder_kernel<<<NBLK, TPB>>>(
        (const float*)d_in[0],   // decoder_inputs
        (const float*)d_in[1],   // alignment_inputs
        (const float*)d_in[2],   // fc_W
        (const float*)d_in[3],   // att_w
        (const float*)d_in[4],   // Wih
        (const float*)d_in[5],   // Whh
        (const float*)d_in[6],   // spec_W
        (const float*)d_in[7],   // spec_b
        (const float*)d_in[8],   // gate_W
        (const float*)d_in[9],   // gate_b
        (float*)d_out);
}